// round 15
// baseline (speedup 1.0000x reference)
#include <cuda_runtime.h>
#include <cstdint>

#define B_     16
#define P_     784
#define D_     10000
#define VROWS  256
#define WPITCH 320
#define GRID   148         // one block per SM -> guaranteed co-resident
#define NG     10          // wordgroups of 32 words (1024 cols each)
#define NSP    14          // p splits of 56
#define PCH    56

// ---- device scratch ----
__device__ unsigned g_vwpack[VROWS * WPITCH];      // packed vw sign bits (320 KB)
__device__ unsigned char g_idx[NSP * 16 * 64];     // level bytes [ch][b][64B]
__device__ unsigned g_part[NSP * 6 * 16 * WPITCH]; // 6-plane partials (1.72 MB)
__device__ unsigned g_bar0, g_bar1, g_bar2;        // barrier counters (self-reset)

__device__ __forceinline__ unsigned maj3(unsigned a, unsigned b, unsigned c) {
    return (a & b) | (a & c) | (b & c);   // single LOP3
}

// Word W: bit l <-> column 128*(W>>2) + 4*l + (W&3)
__global__ __launch_bounds__(512, 2)
void k_all(const float* __restrict__ x,
           const float* __restrict__ pw,
           const float* __restrict__ vw,
           float* __restrict__ out)
{
    __shared__ unsigned vw_s[256 * 32];   // [lev][word] bank=lane  32 KB
    __shared__ unsigned pw_s[PCH * 32];   // [p][word]   bank=lane  7.2 KB
    __shared__ unsigned br_s[16 * 32];    // sign masks [b][word]   2 KB

    const int bid  = blockIdx.x;
    const int t    = threadIdx.x;
    const int wid  = t >> 5;
    const int lane = t & 31;

    // ================= Phase A: pack vw, quantize x =================
    for (int row = bid; row < VROWS; row += GRID) {
        const float* src = vw + (size_t)row * D_;
        float4 f[5];
        #pragma unroll
        for (int k = 0; k < 5; k++) {
            int g5  = wid + k * 16;
            int col = g5 * 128 + lane * 4;
            bool ok = (g5 < 79) && (col + 3 < D_);
            f[k] = ok ? *reinterpret_cast<const float4*>(src + col)
                      : make_float4(1.f, 1.f, 1.f, 1.f);
        }
        #pragma unroll
        for (int k = 0; k < 5; k++) {
            int g5 = wid + k * 16;
            if (g5 < 79) {                         // warp-uniform
                unsigned m0 = __ballot_sync(0xffffffffu, f[k].x < 0.f);
                unsigned m1 = __ballot_sync(0xffffffffu, f[k].y < 0.f);
                unsigned m2 = __ballot_sync(0xffffffffu, f[k].z < 0.f);
                unsigned m3 = __ballot_sync(0xffffffffu, f[k].w < 0.f);
                if (lane < 4) {
                    unsigned mm = (lane == 0) ? m0 : (lane == 1) ? m1
                                 : (lane == 2) ? m2 : m3;
                    g_vwpack[row * WPITCH + g5 * 4 + lane] = mm;
                }
            }
        }
    }
    {   // x quantize (148*512 = 75776 >= 12544, single pass)
        int i = bid * 512 + t;
        if (i < B_ * P_) {
            int b = i / P_, p = i - b * P_;
            int ch = p / PCH, j = p - ch * PCH;
            int q = __float2int_rn(x[i] * 255.0f);  // matches jnp.round (RN-even)
            q = max(0, min(255, q));
            g_idx[(ch * 16 + b) * 64 + j] = (unsigned char)q;
        }
    }

    // ---- barrier 0 ----
    __threadfence();
    __syncthreads();
    if (t == 0) {
        atomicAdd(&g_bar0, 1u);
        while (atomicAdd(&g_bar0, 0u) < GRID) __nanosleep(128);
    }
    __syncthreads();

    // ================= Phase B: pack pw on the fly + accumulate =================
    if (bid < NG * NSP) {
        const int g  = bid / NSP;
        const int sp = bid - g * NSP;

        // packed vw tile from L2 (coalesced)
        for (int i = t; i < 8192; i += 512)
            vw_s[i] = __ldcg(&g_vwpack[(i >> 5) * WPITCH + g * 32 + (i & 31)]);

        // pack pw rows [sp*56, sp*56+56) x cols [1024g, 1024g+1024) from floats
        for (int r = wid; r < PCH; r += 16) {
            const float* src = pw + (size_t)(sp * PCH + r) * D_;
            float4 f[8];
            #pragma unroll
            for (int it = 0; it < 8; it++) {
                int col = g * 1024 + it * 128 + lane * 4;
                f[it] = (col + 3 < D_) ? *reinterpret_cast<const float4*>(src + col)
                                       : make_float4(1.f, 1.f, 1.f, 1.f);
            }
            #pragma unroll
            for (int it = 0; it < 8; it++) {
                unsigned m0 = __ballot_sync(0xffffffffu, f[it].x < 0.f);
                unsigned m1 = __ballot_sync(0xffffffffu, f[it].y < 0.f);
                unsigned m2 = __ballot_sync(0xffffffffu, f[it].z < 0.f);
                unsigned m3 = __ballot_sync(0xffffffffu, f[it].w < 0.f);
                if (lane < 4) {
                    unsigned mm = (lane == 0) ? m0 : (lane == 1) ? m1
                                 : (lane == 2) ? m2 : m3;
                    pw_s[r * 32 + it * 4 + lane] = mm;
                }
            }
        }

        // 56 level bytes for (sp, b=wid) -> registers (warp-uniform)
        unsigned u[14];
        {
            const uint4* ib = reinterpret_cast<const uint4*>(&g_idx[(sp * 16 + wid) * 64]);
            uint4 a0 = __ldcg(ib), a1 = __ldcg(ib + 1), a2 = __ldcg(ib + 2);
            uint2 a3 = __ldcg(reinterpret_cast<const uint2*>(ib + 3));
            u[0]=a0.x; u[1]=a0.y; u[2]=a0.z;  u[3]=a0.w;
            u[4]=a1.x; u[5]=a1.y; u[6]=a1.z;  u[7]=a1.w;
            u[8]=a2.x; u[9]=a2.y; u[10]=a2.z; u[11]=a2.w;
            u[12]=a3.x; u[13]=a3.y;
        }
        __syncthreads();

        // 56 positions = 8 CSA groups of 7; every LDS is bank=lane (zero conflicts)
        unsigned cc0 = 0, cc1 = 0, cc2 = 0, cc3 = 0, cc4 = 0, cc5 = 0;
        #pragma unroll
        for (int gg = 0; gg < 8; gg++) {
            unsigned s[7];
            #pragma unroll
            for (int jj = 0; jj < 7; jj++) {
                int j = gg * 7 + jj;                     // compile-time constant
                unsigned lev = (u[j >> 2] >> ((j & 3) * 8)) & 255u;  // warp-uniform
                s[jj] = vw_s[lev * 32 + lane] ^ pw_s[j * 32 + lane];
            }
            unsigned t1s = s[0] ^ s[1] ^ s[2], t1c = maj3(s[0], s[1], s[2]);
            unsigned t2s = s[3] ^ s[4] ^ s[5], t2c = maj3(s[3], s[4], s[5]);
            unsigned q0  = t1s ^ t2s ^ s[6],   t3c = maj3(t1s, t2s, s[6]);
            unsigned q1  = t1c ^ t2c ^ t3c;
            unsigned q2  = maj3(t1c, t2c, t3c);
            unsigned cr = cc0 & q0;            cc0 ^= q0;
            unsigned n1 = maj3(cc1, q1, cr);   cc1 = cc1 ^ q1 ^ cr;  cr = n1;
            unsigned n2 = maj3(cc2, q2, cr);   cc2 = cc2 ^ q2 ^ cr;  cr = n2;
            unsigned n3 = cc3 & cr;            cc3 ^= cr;            cr = n3;
            unsigned n4 = cc4 & cr;            cc4 ^= cr;            cr = n4;
            cc5 ^= cr;                                               // max 56 < 64
        }

        // coalesced 6-plane partial write
        size_t base = (size_t)((sp * 6) * 16 + wid) * WPITCH + g * 32 + lane;
        g_part[base]               = cc0;
        g_part[base + 16u*WPITCH]  = cc1;
        g_part[base + 32u*WPITCH]  = cc2;
        g_part[base + 48u*WPITCH]  = cc3;
        g_part[base + 64u*WPITCH]  = cc4;
        g_part[base + 80u*WPITCH]  = cc5;
    }

    // ---- barrier 1 (arrive; only phase-C blocks spin) ----
    __threadfence();
    __syncthreads();
    if (t == 0) atomicAdd(&g_bar1, 1u);

    // ================= Phase C: combine 14 splits -> sign, store =================
    if (bid < NG) {
        if (t == 0)
            while (atomicAdd(&g_bar1, 0u) < GRID) __nanosleep(128);
        __syncthreads();

        const int g  = bid;
        const int bl = t >> 5;                 // batch
        const int w  = lane;                   // word

        unsigned P0=0,P1=0,P2=0,P3=0,P4=0,P5=0,P6=0,P7=0,P8=0,P9=0;
        #pragma unroll
        for (int s2 = 0; s2 < NSP; s2++) {
            size_t base = (size_t)((s2 * 6) * 16 + bl) * WPITCH + g * 32 + w;
            unsigned a0 = __ldcg(&g_part[base]);
            unsigned a1 = __ldcg(&g_part[base + 16u*WPITCH]);
            unsigned a2 = __ldcg(&g_part[base + 32u*WPITCH]);
            unsigned a3 = __ldcg(&g_part[base + 48u*WPITCH]);
            unsigned a4 = __ldcg(&g_part[base + 64u*WPITCH]);
            unsigned a5 = __ldcg(&g_part[base + 80u*WPITCH]);
            unsigned cr, n;
            cr = P0 & a0;           P0 ^= a0;
            n = maj3(P1, a1, cr);   P1 = P1 ^ a1 ^ cr;  cr = n;
            n = maj3(P2, a2, cr);   P2 = P2 ^ a2 ^ cr;  cr = n;
            n = maj3(P3, a3, cr);   P3 = P3 ^ a3 ^ cr;  cr = n;
            n = maj3(P4, a4, cr);   P4 = P4 ^ a4 ^ cr;  cr = n;
            n = maj3(P5, a5, cr);   P5 = P5 ^ a5 ^ cr;  cr = n;
            n = P6 & cr;  P6 ^= cr;  cr = n;
            n = P7 & cr;  P7 ^= cr;  cr = n;
            n = P8 & cr;  P8 ^= cr;  cr = n;
            P9 ^= cr;                                    // max 784 < 1024
        }
        // borrow of (cnt - 392); 392 = bits 3,7,8.  br=1 <=> cnt<392 <=> +1
        unsigned br = 0;
        br = ~P0 & br;  br = ~P1 & br;  br = ~P2 & br;
        br = ~P3 | br;
        br = ~P4 & br;  br = ~P5 & br;  br = ~P6 & br;
        br = ~P7 | br;  br = ~P8 | br;
        br = ~P9 & br;
        br_s[bl * 32 + w] = br;
        __syncthreads();

        // coalesced sign store: group g covers cols [1024g, 1024g+1024)
        float* orow = out + (size_t)bl * D_;
        #pragma unroll
        for (int k = 0; k < 8; k++) {
            int col0 = 128 * (g * 8 + k) + 4 * lane;
            if (col0 + 3 < D_) {
                const unsigned* brq = &br_s[bl * 32 + k * 4];
                float4 v;
                v.x = __uint_as_float(0x3F800000u | ((((brq[0] >> lane) & 1u) ^ 1u) << 31));
                v.y = __uint_as_float(0x3F800000u | ((((brq[1] >> lane) & 1u) ^ 1u) << 31));
                v.z = __uint_as_float(0x3F800000u | ((((brq[2] >> lane) & 1u) ^ 1u) << 31));
                v.w = __uint_as_float(0x3F800000u | ((((brq[3] >> lane) & 1u) ^ 1u) << 31));
                *reinterpret_cast<float4*>(orow + col0) = v;
            }
        }
    }

    // ---- barrier 2: completion + counter reset (graph-replay safe) ----
    __syncthreads();
    if (t == 0) {
        atomicAdd(&g_bar2, 1u);
        if (bid == 0) {
            while (atomicAdd(&g_bar2, 0u) < GRID) __nanosleep(128);
            atomicExch(&g_bar0, 0u);
            atomicExch(&g_bar1, 0u);
            atomicExch(&g_bar2, 0u);
            __threadfence();
        }
    }
}

extern "C" void kernel_launch(void* const* d_in, const int* in_sizes, int n_in,
                              void* d_out, int out_size)
{
    (void)in_sizes; (void)n_in; (void)out_size;
    const float* x  = (const float*)d_in[0];   // (16, 28, 28)
    const float* pw = (const float*)d_in[1];   // (784, 10000)
    const float* vw = (const float*)d_in[2];   // (256, 10000)
    float* out = (float*)d_out;                // (16, 10000)

    k_all<<<GRID, 512>>>(x, pw, vw, out);
}

// round 16
// speedup vs baseline: 1.0707x; 1.0707x over previous
#include <cuda_runtime.h>
#include <cstdint>

#define B_    16
#define P_    784
#define D_    10000
#define NW_   316          // packed words per row: 79 groups x 4 (permuted ballot layout)
#define NROW_ 1040         // 784 pw rows + 256 vw rows
#define NPK   296          // persistent k_pack blocks (2/SM), 4 rows each
#define NXB_  25           // extra blocks for x quantize (512 thr each)

// ---- device scratch ----
__device__ unsigned g_packT[NW_ * NROW_];   // TRANSPOSED: [word][row]  (1.31 MB)
__device__ unsigned g_idxr[32 * 16 * 8];    // level bytes [ch][b][32B pitch] (16 KB)

__device__ __forceinline__ unsigned maj3(unsigned a, unsigned b, unsigned c) {
    return (a & b) | (a & c) | (b & c);   // single LOP3
}

__device__ __forceinline__ void loadRow(float4* f, int row,
                                        const float* __restrict__ pw,
                                        const float* __restrict__ vw,
                                        int wid, int lane)
{
    const float* src = (row < P_) ? (pw + (size_t)row * D_)
                                  : (vw + (size_t)(row - P_) * D_);
    bool rok = (row < NROW_);
    #pragma unroll
    for (int k = 0; k < 5; k++) {
        int g   = wid + k * 16;
        int col = g * 128 + lane * 4;
        bool ok = rok && (g < 79) && (col + 3 < D_);
        f[k] = ok ? *reinterpret_cast<const float4*>(src + col)
                  : make_float4(1.f, 1.f, 1.f, 1.f);
    }
}

__device__ __forceinline__ void ballotRow(const float4* f, int row, int wid, int lane)
{
    if (row >= NROW_) return;               // block-uniform
    #pragma unroll
    for (int k = 0; k < 5; k++) {
        int g = wid + k * 16;
        if (g < 79) {                       // warp-uniform
            unsigned m0 = __ballot_sync(0xffffffffu, f[k].x < 0.f);
            unsigned m1 = __ballot_sync(0xffffffffu, f[k].y < 0.f);
            unsigned m2 = __ballot_sync(0xffffffffu, f[k].z < 0.f);
            unsigned m3 = __ballot_sync(0xffffffffu, f[k].w < 0.f);
            if (lane < 4) {
                unsigned mm = (lane == 0) ? m0 : (lane == 1) ? m1
                             : (lane == 2) ? m2 : m3;
                g_packT[(size_t)(g * 4 + lane) * NROW_ + row] = mm;
            }
        }
    }
}

// ============ K1: persistent double-buffered pack + x quantize ============
// Word W: bit l <-> column 128*(W>>2) + 4*l + (W&3)
__global__ __launch_bounds__(512, 2)
void k_pack(const float* __restrict__ x,
            const float* __restrict__ pw,
            const float* __restrict__ vw)
{
    int bid = blockIdx.x;
    int wid = threadIdx.x >> 5, lane = threadIdx.x & 31;

    if (bid < NPK) {
        const int rA = bid, rB = bid + NPK, rC = bid + 2 * NPK, rD = bid + 3 * NPK;
        float4 fa[5], fb[5];
        loadRow(fa, rA, pw, vw, wid, lane);     // always valid
        loadRow(fb, rB, pw, vw, wid, lane);
        ballotRow(fa, rA, wid, lane);           // fb in flight
        loadRow(fa, rC, pw, vw, wid, lane);
        ballotRow(fb, rB, wid, lane);           // fa(rC) in flight
        loadRow(fb, rD, pw, vw, wid, lane);
        ballotRow(fa, rC, wid, lane);           // fb(rD) in flight
        ballotRow(fb, rD, wid, lane);
    } else {
        int i = (bid - NPK) * 512 + threadIdx.x;
        if (i < B_ * P_) {
            int b = i / P_, p = i - b * P_;
            int ch, j;
            if (p < 400) { ch = p / 25;              j = p - ch * 25; }
            else         { ch = 16 + (p - 400) / 24; j = (p - 400) - (ch - 16) * 24; }
            int q = __float2int_rn(x[i] * 255.0f);   // matches jnp.round (RN-even)
            q = max(0, min(255, q));
            reinterpret_cast<unsigned char*>(g_idxr)[((ch * 16 + b) << 5) + j] =
                (unsigned char)q;
        }
    }
}

// ============ K2 (fused): accumulate + combine + compare + store ============
// One block per word (316 blocks x 512 threads). 32 p-chunks (16x25 + 16x24).
// EXACT R6 version (regs 32, measured 9.02us).
__global__ __launch_bounds__(512)
void k_acc(float* __restrict__ out)
{
    __shared__ unsigned pv_s[NROW_];        // pw bits [0..783], vw bits [784..1039]
    __shared__ unsigned part2[16][16][7];   // [warp][b][6 planes] pad 7 (7.2 KB)
    __shared__ unsigned br_s[16];

    const int w   = blockIdx.x;
    const int t   = threadIdx.x;
    const int wid = t >> 5, lane = t & 31;

    const unsigned* colbase = g_packT + (size_t)w * NROW_;
    for (int i = t; i < NROW_; i += 512) pv_s[i] = colbase[i];

    // thread = (b, chunk): chunk = wid*2 + (lane>>4); warps 0-7 len 25, 8-15 len 24
    const int b   = lane & 15;
    const int ph  = lane >> 4;
    const int ch  = wid * 2 + ph;
    const int start = (wid < 8) ? ch * 25 : 400 + (ch - 16) * 24;

    unsigned u[8];
    {
        const uint4* src = reinterpret_cast<const uint4*>(g_idxr + (ch * 16 + b) * 8);
        uint4 a0 = src[0], a1 = src[1];
        u[0]=a0.x; u[1]=a0.y; u[2]=a0.z; u[3]=a0.w;
        u[4]=a1.x; u[5]=a1.y; u[6]=a1.z; u[7]=a1.w;
    }
    __syncthreads();

    const unsigned* vw_s = pv_s + P_;
    const unsigned* ppwr = pv_s + start;
    unsigned cc0 = 0, cc1 = 0, cc2 = 0, cc3 = 0, cc4 = 0;

    // 3 groups of 7
    #pragma unroll
    for (int g = 0; g < 3; g++) {
        unsigned s[7];
        #pragma unroll
        for (int jj = 0; jj < 7; jj++) {
            int j = g * 7 + jj;                       // compile-time constant
            unsigned lev = (u[j >> 2] >> ((j & 3) * 8)) & 255u;
            s[jj] = vw_s[lev] ^ ppwr[j];
        }
        unsigned t1s = s[0] ^ s[1] ^ s[2], t1c = maj3(s[0], s[1], s[2]);
        unsigned t2s = s[3] ^ s[4] ^ s[5], t2c = maj3(s[3], s[4], s[5]);
        unsigned q0  = t1s ^ t2s ^ s[6],   t3c = maj3(t1s, t2s, s[6]);
        unsigned q1  = t1c ^ t2c ^ t3c;
        unsigned q2  = maj3(t1c, t2c, t3c);
        unsigned c = cc0 & q0;            cc0 ^= q0;
        unsigned n1 = maj3(cc1, q1, c);   cc1 = cc1 ^ q1 ^ c;  c = n1;
        unsigned n2 = maj3(cc2, q2, c);   cc2 = cc2 ^ q2 ^ c;  c = n2;
        unsigned n3 = cc3 & c;            cc3 ^= c;            c = n3;
        cc4 ^= c;
    }
    // remainder: positions 21,22,23 (CSA3) + 24 if len==25
    {
        unsigned l0 = (u[5] >>  8) & 255u;            // j=21
        unsigned l1 = (u[5] >> 16) & 255u;            // j=22
        unsigned l2 = (u[5] >> 24) & 255u;            // j=23
        unsigned s0 = vw_s[l0] ^ ppwr[21];
        unsigned s1 = vw_s[l1] ^ ppwr[22];
        unsigned s2 = vw_s[l2] ^ ppwr[23];
        unsigned q0 = s0 ^ s1 ^ s2, q1 = maj3(s0, s1, s2);
        unsigned c = cc0 & q0;            cc0 ^= q0;
        unsigned n1 = maj3(cc1, q1, c);   cc1 = cc1 ^ q1 ^ c;  c = n1;
        unsigned n2 = cc2 & c;            cc2 ^= c;            c = n2;
        unsigned n3 = cc3 & c;            cc3 ^= c;            c = n3;
        cc4 ^= c;
        if (wid < 8) {                                // warp-uniform
            unsigned l3 = u[6] & 255u;                // j=24
            unsigned s3 = vw_s[l3] ^ ppwr[24];
            unsigned cr = cc0 & s3;  cc0 ^= s3;
            unsigned m1 = cc1 & cr;  cc1 ^= cr;  cr = m1;
            unsigned m2 = cc2 & cr;  cc2 ^= cr;  cr = m2;
            unsigned m3 = cc3 & cr;  cc3 ^= cr;  cr = m3;
            cc4 ^= cr;                                // max 25 < 32
        }
    }

    // combine chunk pair (lane ^ 16): 5+5 planes -> 6 planes (max 49)
    {
        unsigned d0 = __shfl_xor_sync(0xffffffffu, cc0, 16);
        unsigned d1 = __shfl_xor_sync(0xffffffffu, cc1, 16);
        unsigned d2 = __shfl_xor_sync(0xffffffffu, cc2, 16);
        unsigned d3 = __shfl_xor_sync(0xffffffffu, cc3, 16);
        unsigned d4 = __shfl_xor_sync(0xffffffffu, cc4, 16);
        unsigned c, n;
        c = cc0 & d0;            cc0 ^= d0;
        n = maj3(cc1, d1, c);    cc1 = cc1 ^ d1 ^ c;  c = n;
        n = maj3(cc2, d2, c);    cc2 = cc2 ^ d2 ^ c;  c = n;
        n = maj3(cc3, d3, c);    cc3 = cc3 ^ d3 ^ c;  c = n;
        n = maj3(cc4, d4, c);    cc4 = cc4 ^ d4 ^ c;  c = n;
        if (lane < 16) {
            unsigned* pr = part2[wid][b];
            pr[0]=cc0; pr[1]=cc1; pr[2]=cc2; pr[3]=cc3; pr[4]=cc4; pr[5]=c;
        }
    }
    __syncthreads();

    // threads 0..15: combine 16 warps' 6-plane partials -> 10 planes, compare vs 392
    if (t < 16) {
        unsigned P0=0,P1=0,P2=0,P3=0,P4=0,P5=0,P6=0,P7=0,P8=0,P9=0;
        #pragma unroll
        for (int k = 0; k < 16; k++) {
            const unsigned* a = part2[k][t];
            unsigned c, n;
            c = P0 & a[0];           P0 ^= a[0];
            n = maj3(P1, a[1], c);   P1 = P1 ^ a[1] ^ c;  c = n;
            n = maj3(P2, a[2], c);   P2 = P2 ^ a[2] ^ c;  c = n;
            n = maj3(P3, a[3], c);   P3 = P3 ^ a[3] ^ c;  c = n;
            n = maj3(P4, a[4], c);   P4 = P4 ^ a[4] ^ c;  c = n;
            n = maj3(P5, a[5], c);   P5 = P5 ^ a[5] ^ c;  c = n;
            n = P6 & c;  P6 ^= c;  c = n;
            n = P7 & c;  P7 ^= c;  c = n;
            n = P8 & c;  P8 ^= c;  c = n;
            P9 ^= c;                                       // max 784 < 1024
        }
        // borrow of (cnt - 392); 392 = bits 3,7,8.  br=1 <=> cnt<392 <=> +1
        unsigned br = 0;
        br = ~P0 & br;  br = ~P1 & br;  br = ~P2 & br;
        br = ~P3 | br;
        br = ~P4 & br;  br = ~P5 & br;  br = ~P6 & br;
        br = ~P7 | br;  br = ~P8 | br;
        br = ~P9 & br;
        br_s[t] = br;
    }
    __syncthreads();

    // store: 512 signs (16 b x 32 bits), 1 per thread
    {
        int bb = t >> 5;
        int j  = t & 31;
        unsigned br = br_s[bb];
        int col = 128 * (w >> 2) + (w & 3) + 4 * j;
        if (col < D_) {
            unsigned sgn = ((br >> j) & 1u) ^ 1u;
            out[(size_t)bb * D_ + col] = __uint_as_float(0x3F800000u | (sgn << 31));
        }
    }
}

extern "C" void kernel_launch(void* const* d_in, const int* in_sizes, int n_in,
                              void* d_out, int out_size)
{
    (void)in_sizes; (void)n_in; (void)out_size;
    const float* x  = (const float*)d_in[0];   // (16, 28, 28)
    const float* pw = (const float*)d_in[1];   // (784, 10000)
    const float* vw = (const float*)d_in[2];   // (256, 10000)
    float* out = (float*)d_out;                // (16, 10000)

    k_pack<<<NPK + NXB_, 512>>>(x, pw, vw);
    k_acc<<<NW_, 512>>>(out);
}

// round 17
// speedup vs baseline: 1.4133x; 1.3200x over previous
#include <cuda_runtime.h>
#include <cstdint>

#define B_   16
#define P_   784
#define D_   10000
#define NWB  313           // one block per 32-column word

__device__ __forceinline__ unsigned maj3(unsigned a, unsigned b, unsigned c) {
    return (a & b) | (a & c) | (b & c);   // single LOP3
}

// Fully fused: quantize + pack (natural layout) + CSA accumulate + sign store.
// Block w covers columns [32w, 32w+32); ballot bit l <-> column 32w+l.
__global__ __launch_bounds__(512, 3)
void k_fused(const float* __restrict__ x,
             const float* __restrict__ pw,
             const float* __restrict__ vw,
             float* __restrict__ out)
{
    __shared__ unsigned vw_s[256];            // packed vw bits     1 KB
    __shared__ unsigned pw_s[P_];             // packed pw bits     3.1 KB
    __shared__ unsigned char idx_s[32*16*32]; // levels [ch][b][32] 16 KB
    __shared__ unsigned part2[16][16][7];     // [warp][b][6 planes] 7.2 KB
    __shared__ unsigned br_s[16];

    const int w    = blockIdx.x;
    const int t    = threadIdx.x;
    const int wid  = t >> 5, lane = t & 31;
    const int col  = w * 32 + lane;
    const bool ok  = (col < D_);

    // ---- quantize x -> idx_s [ch][b][32B] (L1-hot, coalesced) ----
    for (int i = t; i < B_ * P_; i += 512) {
        int b = i / P_, p = i - b * P_;
        int ch, j;
        if (p < 400) { ch = p / 25;              j = p - ch * 25; }
        else         { ch = 16 + (p - 400) / 24; j = (p - 400) - (ch - 16) * 24; }
        int q = __float2int_rn(x[i] * 255.0f);   // matches jnp.round (RN-even)
        q = max(0, min(255, q));
        idx_s[((ch * 16 + b) << 5) + j] = (unsigned char)q;
    }

    // ---- pack vw slice: warp wid does rows wid + 16k (16 rows), MLP=8 ----
    #pragma unroll
    for (int half = 0; half < 2; half++) {
        float f[8];
        #pragma unroll
        for (int k = 0; k < 8; k++) {
            int row = wid + (half * 8 + k) * 16;
            f[k] = ok ? __ldcs(vw + (size_t)row * D_ + col) : 1.0f;
        }
        #pragma unroll
        for (int k = 0; k < 8; k++) {
            int row = wid + (half * 8 + k) * 16;
            unsigned m = __ballot_sync(0xffffffffu, f[k] < 0.0f);
            if (lane == 0) vw_s[row] = m;
        }
    }
    // ---- pack pw slice: warp wid does rows wid + 16k (49 rows), MLP=8 ----
    #pragma unroll
    for (int kb = 0; kb < 6; kb++) {
        float f[8];
        #pragma unroll
        for (int k = 0; k < 8; k++) {
            int row = wid + (kb * 8 + k) * 16;
            f[k] = ok ? __ldcs(pw + (size_t)row * D_ + col) : 1.0f;
        }
        #pragma unroll
        for (int k = 0; k < 8; k++) {
            int row = wid + (kb * 8 + k) * 16;
            unsigned m = __ballot_sync(0xffffffffu, f[k] < 0.0f);
            if (lane == 0) pw_s[row] = m;
        }
    }
    {   // last pw row: k=48 -> row = wid + 768
        int row = wid + 768;
        float fl = ok ? __ldcs(pw + (size_t)row * D_ + col) : 1.0f;
        unsigned m = __ballot_sync(0xffffffffu, fl < 0.0f);
        if (lane == 0) pw_s[row] = m;
    }
    __syncthreads();

    // ---- accumulate: thread = (b, chunk); warps 0-7 len 25, 8-15 len 24 ----
    const int b   = lane & 15;
    const int ph  = lane >> 4;
    const int ch  = wid * 2 + ph;
    const int start = (wid < 8) ? ch * 25 : 400 + (ch - 16) * 24;

    unsigned u[8];
    {
        const uint4* s4 = reinterpret_cast<const uint4*>(idx_s + ((ch * 16 + b) << 5));
        uint4 a0 = s4[0], a1 = s4[1];
        u[0]=a0.x; u[1]=a0.y; u[2]=a0.z; u[3]=a0.w;
        u[4]=a1.x; u[5]=a1.y; u[6]=a1.z; u[7]=a1.w;
    }

    const unsigned* ppwr = pw_s + start;
    unsigned cc0 = 0, cc1 = 0, cc2 = 0, cc3 = 0, cc4 = 0;

    #pragma unroll
    for (int g = 0; g < 3; g++) {             // 3 CSA groups of 7 -> 21
        unsigned s[7];
        #pragma unroll
        for (int jj = 0; jj < 7; jj++) {
            int j = g * 7 + jj;                           // compile-time constant
            unsigned lev = (u[j >> 2] >> ((j & 3) * 8)) & 255u;
            s[jj] = vw_s[lev] ^ ppwr[j];
        }
        unsigned t1s = s[0] ^ s[1] ^ s[2], t1c = maj3(s[0], s[1], s[2]);
        unsigned t2s = s[3] ^ s[4] ^ s[5], t2c = maj3(s[3], s[4], s[5]);
        unsigned q0  = t1s ^ t2s ^ s[6],   t3c = maj3(t1s, t2s, s[6]);
        unsigned q1  = t1c ^ t2c ^ t3c;
        unsigned q2  = maj3(t1c, t2c, t3c);
        unsigned c = cc0 & q0;            cc0 ^= q0;
        unsigned n1 = maj3(cc1, q1, c);   cc1 = cc1 ^ q1 ^ c;  c = n1;
        unsigned n2 = maj3(cc2, q2, c);   cc2 = cc2 ^ q2 ^ c;  c = n2;
        unsigned n3 = cc3 & c;            cc3 ^= c;            c = n3;
        cc4 ^= c;
    }
    {   // remainder: 21,22,23 (CSA3) + 24 if len==25
        unsigned l0 = (u[5] >>  8) & 255u;
        unsigned l1 = (u[5] >> 16) & 255u;
        unsigned l2 = (u[5] >> 24) & 255u;
        unsigned s0 = vw_s[l0] ^ ppwr[21];
        unsigned s1 = vw_s[l1] ^ ppwr[22];
        unsigned s2 = vw_s[l2] ^ ppwr[23];
        unsigned q0 = s0 ^ s1 ^ s2, q1 = maj3(s0, s1, s2);
        unsigned c = cc0 & q0;            cc0 ^= q0;
        unsigned n1 = maj3(cc1, q1, c);   cc1 = cc1 ^ q1 ^ c;  c = n1;
        unsigned n2 = cc2 & c;            cc2 ^= c;            c = n2;
        unsigned n3 = cc3 & c;            cc3 ^= c;            c = n3;
        cc4 ^= c;
        if (wid < 8) {                            // warp-uniform: len-25 chunks
            unsigned l3 = u[6] & 255u;            // j=24
            unsigned s3 = vw_s[l3] ^ ppwr[24];
            unsigned cr = cc0 & s3;  cc0 ^= s3;
            unsigned m1 = cc1 & cr;  cc1 ^= cr;  cr = m1;
            unsigned m2 = cc2 & cr;  cc2 ^= cr;  cr = m2;
            unsigned m3 = cc3 & cr;  cc3 ^= cr;  cr = m3;
            cc4 ^= cr;                            // max 25 < 32
        }
    }

    // ---- combine chunk pair (lane ^ 16): 5+5 planes -> 6 (max 49) ----
    {
        unsigned d0 = __shfl_xor_sync(0xffffffffu, cc0, 16);
        unsigned d1 = __shfl_xor_sync(0xffffffffu, cc1, 16);
        unsigned d2 = __shfl_xor_sync(0xffffffffu, cc2, 16);
        unsigned d3 = __shfl_xor_sync(0xffffffffu, cc3, 16);
        unsigned d4 = __shfl_xor_sync(0xffffffffu, cc4, 16);
        unsigned c, n;
        c = cc0 & d0;            cc0 ^= d0;
        n = maj3(cc1, d1, c);    cc1 = cc1 ^ d1 ^ c;  c = n;
        n = maj3(cc2, d2, c);    cc2 = cc2 ^ d2 ^ c;  c = n;
        n = maj3(cc3, d3, c);    cc3 = cc3 ^ d3 ^ c;  c = n;
        n = maj3(cc4, d4, c);    cc4 = cc4 ^ d4 ^ c;  c = n;
        if (lane < 16) {
            unsigned* pr = part2[wid][b];
            pr[0]=cc0; pr[1]=cc1; pr[2]=cc2; pr[3]=cc3; pr[4]=cc4; pr[5]=c;
        }
    }
    __syncthreads();

    // ---- threads 0..15: combine 16 warps -> 10 planes, compare vs 392 ----
    if (t < 16) {
        unsigned P0=0,P1=0,P2=0,P3=0,P4=0,P5=0,P6=0,P7=0,P8=0,P9=0;
        #pragma unroll
        for (int k = 0; k < 16; k++) {
            const unsigned* a = part2[k][t];
            unsigned c, n;
            c = P0 & a[0];           P0 ^= a[0];
            n = maj3(P1, a[1], c);   P1 = P1 ^ a[1] ^ c;  c = n;
            n = maj3(P2, a[2], c);   P2 = P2 ^ a[2] ^ c;  c = n;
            n = maj3(P3, a[3], c);   P3 = P3 ^ a[3] ^ c;  c = n;
            n = maj3(P4, a[4], c);   P4 = P4 ^ a[4] ^ c;  c = n;
            n = maj3(P5, a[5], c);   P5 = P5 ^ a[5] ^ c;  c = n;
            n = P6 & c;  P6 ^= c;  c = n;
            n = P7 & c;  P7 ^= c;  c = n;
            n = P8 & c;  P8 ^= c;  c = n;
            P9 ^= c;                                       // max 784 < 1024
        }
        // borrow of (cnt - 392); 392 = bits 3,7,8.  br=1 <=> cnt<392 <=> +1
        unsigned br = 0;
        br = ~P0 & br;  br = ~P1 & br;  br = ~P2 & br;
        br = ~P3 | br;
        br = ~P4 & br;  br = ~P5 & br;  br = ~P6 & br;
        br = ~P7 | br;  br = ~P8 | br;
        br = ~P9 & br;
        br_s[t] = br;
    }
    __syncthreads();

    // ---- sign store: thread = (b, bit); coalesced 128B per warp ----
    {
        int bb = t >> 5;
        int j  = t & 31;
        int co = w * 32 + j;                   // natural layout
        if (co < D_) {
            unsigned sgn = ((br_s[bb] >> j) & 1u) ^ 1u;
            out[(size_t)bb * D_ + co] = __uint_as_float(0x3F800000u | (sgn << 31));
        }
    }
}

extern "C" void kernel_launch(void* const* d_in, const int* in_sizes, int n_in,
                              void* d_out, int out_size)
{
    (void)in_sizes; (void)n_in; (void)out_size;
    const float* x  = (const float*)d_in[0];   // (16, 28, 28)
    const float* pw = (const float*)d_in[1];   // (784, 10000)
    const float* vw = (const float*)d_in[2];   // (256, 10000)
    float* out = (float*)d_out;                // (16, 10000)

    k_fused<<<NWB, 512>>>(x, pw, vw, out);
}